// round 16
// baseline (speedup 1.0000x reference)
#include <cuda_runtime.h>
#include <cstdint>

#define DIM    768
#define NEXP   8
#define PARTS  8                      // lanes cooperating per token
#define TOKB   16                     // tokens per block (one 48KB bulk load)
#define TPB    64
#define JITER  (DIM / (PARTS * 4))    // 24 float4-steps per part
#define ROWQ   (DIM / 4)              // 192 ulonglong2 per token row

#define W_BYTES   (NEXP * DIM * 4)            // 24576
#define OFF_BIAS  W_BYTES                     // 24576 (32B)
#define OFF_MBAR  (W_BYTES + 32)              // 24608 (8B aligned)
#define OFF_X     24704                       // 128B aligned
#define X_BYTES   (TOKB * DIM * 4)            // 49152
#define SMEM_TOTAL (OFF_X + X_BYTES)          // 73856 -> 3 blocks/SM

// Packed fp32x2 math (Blackwell): one instruction, two fp32 FMAs.
__device__ __forceinline__ unsigned long long ffma2(unsigned long long a,
                                                    unsigned long long b,
                                                    unsigned long long c) {
    unsigned long long d;
    asm("fma.rn.f32x2 %0, %1, %2, %3;" : "=l"(d) : "l"(a), "l"(b), "l"(c));
    return d;
}
__device__ __forceinline__ unsigned long long fadd2(unsigned long long a,
                                                    unsigned long long b) {
    unsigned long long d;
    asm("add.rn.f32x2 %0, %1, %2;" : "=l"(d) : "l"(a), "l"(b));
    return d;
}
__device__ __forceinline__ uint32_t smem_u32(const void* p) {
    uint32_t a;
    asm("{ .reg .u64 t; cvta.to.shared.u64 t, %1; cvt.u32.u64 %0, t; }"
        : "=r"(a) : "l"(p));
    return a;
}

__global__ __launch_bounds__(TPB)
void Router_54932631716286_kernel(const float* __restrict__ x,
                                  const float* __restrict__ W,
                                  const float* __restrict__ b,
                                  float* __restrict__ out,
                                  int n_tokens)
{
    extern __shared__ char smem[];
    const int tid = threadIdx.x;

    const uint32_t mbar = smem_u32(smem + OFF_MBAR);
    if (tid == 0)
        asm volatile("mbarrier.init.shared.b64 [%0], 1;" :: "r"(mbar) : "memory");
    __syncthreads();          // mbar init visible before expect/arrivals

    // One bulk-DMA request for this block's whole x tile (contiguous 48KB).
    const int base_tok = blockIdx.x * TOKB;
    const int ntok     = min(TOKB, n_tokens - base_tok);
    const uint32_t xbytes = (uint32_t)ntok * DIM * 4;
    if (tid == 0) {
        asm volatile("mbarrier.arrive.expect_tx.shared.b64 _, [%0], %1;"
                     :: "r"(mbar), "r"(xbytes) : "memory");
        asm volatile(
            "cp.async.bulk.shared::cluster.global.mbarrier::complete_tx::bytes "
            "[%0], [%1], %2, [%3];"
            :: "r"(smem_u32(smem + OFF_X)), "l"(x + (size_t)base_tok * DIM),
               "r"(xbytes), "r"(mbar) : "memory");
    }

    // Stage W (24KB) + bias with regular loads while the bulk copy flies.
    {
        const float4* Wg = reinterpret_cast<const float4*>(W);
        float4* Ws = reinterpret_cast<float4*>(smem);
        for (int i = tid; i < NEXP * DIM / 4; i += TPB) Ws[i] = Wg[i];
        float* sbw = reinterpret_cast<float*>(smem + OFF_BIAS);
        if (tid < NEXP) sbw[tid] = b[tid];
    }
    __syncthreads();          // W visible to all

    // Wait for the x tile (phase 0).
    asm volatile(
        "{\n\t.reg .pred P;\n\t"
        "W%=:\n\tmbarrier.try_wait.parity.acquire.cta.shared::cta.b64 P, [%0], 0, 0x989680;\n\t"
        "@P bra.uni D%=;\n\tbra.uni W%=;\n\tD%=:\n\t}"
        :: "r"(mbar) : "memory");

    const int group = tid >> 3;            // 8 groups x 2 tokens = 16 tokens
    const int part  = tid & 7;
    const int lt0   = 2 * group;           // local token index

    // Clamp local rows for a ragged final block (exact fit for N=25216).
    const int lr0 = (lt0     < ntok) ? lt0     : 0;
    const int lr1 = (lt0 + 1 < ntok) ? lt0 + 1 : lr0;

    const ulonglong2* xr0 = reinterpret_cast<const ulonglong2*>(smem + OFF_X + lr0 * DIM * 4);
    const ulonglong2* xr1 = reinterpret_cast<const ulonglong2*>(smem + OFF_X + lr1 * DIM * 4);
    const ulonglong2* wp  = reinterpret_cast<const ulonglong2*>(smem);
    const float*      sb  = reinterpret_cast<const float*>(smem + OFF_BIAS);

    unsigned long long acc[NEXP][2];
#pragma unroll
    for (int e = 0; e < NEXP; e++) { acc[e][0] = 0ull; acc[e][1] = 0ull; }

#pragma unroll
    for (int j = 0; j < JITER; j++) {
        const int i = part + j * PARTS;
        ulonglong2 x0 = xr0[i];            // 29-cyc smem latency, trivially hidden
        ulonglong2 x1 = xr1[i];
#pragma unroll
        for (int e = 0; e < NEXP; e++) {
            ulonglong2 wv = wp[e * ROWQ + i];   // uniform index: 1-wavefront bcast
            acc[e][0] = ffma2(x0.x, wv.x, ffma2(x0.y, wv.y, acc[e][0]));
            acc[e][1] = ffma2(x1.x, wv.x, ffma2(x1.y, wv.y, acc[e][1]));
        }
    }

    // Reduce the 8 part-partials (consecutive lanes) via butterfly shuffles.
#pragma unroll
    for (int e = 0; e < NEXP; e++) {
#pragma unroll
        for (int t = 0; t < 2; t++) {
            unsigned long long v = acc[e][t];
            v = fadd2(v, __shfl_xor_sync(0xffffffffu, v, 1));
            v = fadd2(v, __shfl_xor_sync(0xffffffffu, v, 2));
            v = fadd2(v, __shfl_xor_sync(0xffffffffu, v, 4));
            acc[e][t] = v;
        }
    }

    const int t0 = base_tok + lt0;
    if (part != 0 || t0 >= n_tokens) return;

    // Epilogue: softmax + top-2 for this group's 2 tokens.
    float4 gv, iv;
    float* gvf = reinterpret_cast<float*>(&gv);
    float* ivf = reinterpret_cast<float*>(&iv);

#pragma unroll
    for (int t = 0; t < 2; t++) {
        float logits[NEXP];
        float m = -1e30f;
#pragma unroll
        for (int e = 0; e < NEXP; e++) {
            float lo = __uint_as_float((unsigned)(acc[e][t] & 0xffffffffull));
            float hi = __uint_as_float((unsigned)(acc[e][t] >> 32));
            logits[e] = lo + hi + sb[e];
            m = fmaxf(m, logits[e]);
        }
        float g[NEXP], s = 0.f;
#pragma unroll
        for (int e = 0; e < NEXP; e++) { g[e] = __expf(logits[e] - m); s += g[e]; }
        float inv = 1.0f / s;
#pragma unroll
        for (int e = 0; e < NEXP; e++) g[e] *= inv;

        // Top-2, strict '>' keeps lowest index on ties (matches jax.lax.top_k).
        int i1 = 0; float g1 = g[0];
#pragma unroll
        for (int e = 1; e < NEXP; e++) if (g[e] > g1) { g1 = g[e]; i1 = e; }
        int i2 = -1; float g2 = -1e30f;
#pragma unroll
        for (int e = 0; e < NEXP; e++) if (e != i1 && g[e] > g2) { g2 = g[e]; i2 = e; }

        gvf[2 * t + 0] = g1;
        gvf[2 * t + 1] = g2;
        ivf[2 * t + 0] = (float)i1;
        ivf[2 * t + 1] = (float)i2;
    }

    // Output: [0,2N) top-2 gates, [2N,4N) indices as fp32 (exact integers).
    // t0 even -> out + t0*2 is 16B aligned -> one float4 per stream.
    float* og = out + (size_t)t0 * 2;
    float* oi = out + (size_t)2 * n_tokens + (size_t)t0 * 2;
    if (t0 + 1 < n_tokens) {
        *reinterpret_cast<float4*>(og) = gv;
        *reinterpret_cast<float4*>(oi) = iv;
    } else {
        og[0] = gvf[0]; og[1] = gvf[1];
        oi[0] = ivf[0]; oi[1] = ivf[1];
    }
}

extern "C" void kernel_launch(void* const* d_in, const int* in_sizes, int n_in,
                              void* d_out, int out_size) {
    const float* x = (const float*)d_in[0];
    const float* W = (const float*)d_in[1];
    const float* b = (const float*)d_in[2];
    float* out = (float*)d_out;

    int n_tokens = in_sizes[0] / DIM;                  // 128*197 = 25216
    int blocks   = (n_tokens + TOKB - 1) / TOKB;       // 1576 (exact fit)

    static int attr_done = 0;
    if (!attr_done) {
        cudaFuncSetAttribute(Router_54932631716286_kernel,
                             cudaFuncAttributeMaxDynamicSharedMemorySize, SMEM_TOTAL);
        attr_done = 1;
    }
    Router_54932631716286_kernel<<<blocks, TPB, SMEM_TOTAL>>>(x, W, b, out, n_tokens);
}

// round 17
// speedup vs baseline: 1.5802x; 1.5802x over previous
#include <cuda_runtime.h>

#define DIM    768
#define NEXP   8
#define PARTS  8                      // threads cooperating per token
#define TOKS   4                      // tokens per thread
#define JITER  (DIM / (PARTS * 4))    // float4 iterations per part = 24
#define TPB    64

// Packed fp32x2 math (Blackwell): one instruction, two fp32 FMAs.
__device__ __forceinline__ unsigned long long ffma2(unsigned long long a,
                                                    unsigned long long b,
                                                    unsigned long long c) {
    unsigned long long d;
    asm("fma.rn.f32x2 %0, %1, %2, %3;" : "=l"(d) : "l"(a), "l"(b), "l"(c));
    return d;
}
__device__ __forceinline__ unsigned long long fadd2(unsigned long long a,
                                                    unsigned long long b) {
    unsigned long long d;
    asm("add.rn.f32x2 %0, %1, %2;" : "=l"(d) : "l"(a), "l"(b));
    return d;
}

// Volatile 16B global load with L2 evict_last: volatile pins SASS issue order,
// so both prefetch buffers (8 LDG.128 = 4KB/warp) are provably in flight.
__device__ __forceinline__ ulonglong2 ldg_pin(const ulonglong2* p,
                                              unsigned long long pol) {
    ulonglong2 v;
    asm volatile("ld.global.L2::cache_hint.v2.u64 {%0, %1}, [%2], %3;"
                 : "=l"(v.x), "=l"(v.y) : "l"(p), "l"(pol));
    return v;
}

__global__ __launch_bounds__(TPB)
void Router_54932631716286_kernel(const float* __restrict__ x,
                                  const float* __restrict__ W,
                                  const float* __restrict__ b,
                                  float* __restrict__ out,
                                  int n_tokens)
{
    // W: 8 x 768 fp32 = 24 KB staged in smem; uniform index across the warp's
    // 4 token-groups -> each LDS.128 touches 128B unique = 1 wavefront.
    __shared__ float4 sW4[NEXP * DIM / 4];
    __shared__ float  sb[NEXP];

    const float4* W4 = reinterpret_cast<const float4*>(W);
    for (int i = threadIdx.x; i < NEXP * DIM / 4; i += TPB) sW4[i] = W4[i];
    if (threadIdx.x < NEXP) sb[threadIdx.x] = b[threadIdx.x];
    __syncthreads();

    unsigned long long pol;
    asm("createpolicy.fractional.L2::evict_last.b64 %0, 1.0;" : "=l"(pol));

    int gtid  = blockIdx.x * TPB + threadIdx.x;
    int group = gtid >> 3;            // 8 consecutive lanes share a 4-token group
    int part  = gtid & 7;
    int t0    = group * TOKS;

    if (t0 >= n_tokens) return;       // group-aligned warp exit

    // Clamped per-token row pointers (ragged-tail safe).
    int tr1 = (t0 + 1 < n_tokens) ? t0 + 1 : t0;
    int tr2 = (t0 + 2 < n_tokens) ? t0 + 2 : t0;
    int tr3 = (t0 + 3 < n_tokens) ? t0 + 3 : t0;

    const ulonglong2* xr0 = reinterpret_cast<const ulonglong2*>(x + (size_t)t0  * DIM);
    const ulonglong2* xr1 = reinterpret_cast<const ulonglong2*>(x + (size_t)tr1 * DIM);
    const ulonglong2* xr2 = reinterpret_cast<const ulonglong2*>(x + (size_t)tr2 * DIM);
    const ulonglong2* xr3 = reinterpret_cast<const ulonglong2*>(x + (size_t)tr3 * DIM);
    const ulonglong2* wp  = reinterpret_cast<const ulonglong2*>(sW4);

    unsigned long long acc[NEXP][TOKS];
#pragma unroll
    for (int e = 0; e < NEXP; e++)
#pragma unroll
        for (int t = 0; t < TOKS; t++) acc[e][t] = 0ull;

    // Depth-2 software pipeline with two ALTERNATING buffers (A: even j,
    // B: odd j). No inter-buffer register shifting -> no serializing MOV
    // chains; volatile loads keep 8 LDG.128 outstanding per warp.
    int i = part;
    ulonglong2 A0 = ldg_pin(xr0 + i, pol);
    ulonglong2 A1 = ldg_pin(xr1 + i, pol);
    ulonglong2 A2 = ldg_pin(xr2 + i, pol);
    ulonglong2 A3 = ldg_pin(xr3 + i, pol);
    ulonglong2 B0 = ldg_pin(xr0 + i + PARTS, pol);
    ulonglong2 B1 = ldg_pin(xr1 + i + PARTS, pol);
    ulonglong2 B2 = ldg_pin(xr2 + i + PARTS, pol);
    ulonglong2 B3 = ldg_pin(xr3 + i + PARTS, pol);

#pragma unroll
    for (int j = 0; j < JITER; j += 2) {
        // ---- even step: consume A, refill A for j+2 first (loads lead FMAs)
        ulonglong2 x0 = A0, x1 = A1, x2 = A2, x3 = A3;
        if (j + 2 < JITER) {
            A0 = ldg_pin(xr0 + i + 2 * PARTS, pol);
            A1 = ldg_pin(xr1 + i + 2 * PARTS, pol);
            A2 = ldg_pin(xr2 + i + 2 * PARTS, pol);
            A3 = ldg_pin(xr3 + i + 2 * PARTS, pol);
        }
#pragma unroll
        for (int e = 0; e < NEXP; e++) {
            ulonglong2 wv = wp[e * (DIM / 4) + i];
            acc[e][0] = ffma2(x0.x, wv.x, ffma2(x0.y, wv.y, acc[e][0]));
            acc[e][1] = ffma2(x1.x, wv.x, ffma2(x1.y, wv.y, acc[e][1]));
            acc[e][2] = ffma2(x2.x, wv.x, ffma2(x2.y, wv.y, acc[e][2]));
            acc[e][3] = ffma2(x3.x, wv.x, ffma2(x3.y, wv.y, acc[e][3]));
        }

        // ---- odd step: consume B, refill B for j+3
        ulonglong2 y0 = B0, y1 = B1, y2 = B2, y3 = B3;
        if (j + 3 < JITER) {
            B0 = ldg_pin(xr0 + i + 3 * PARTS, pol);
            B1 = ldg_pin(xr1 + i + 3 * PARTS, pol);
            B2 = ldg_pin(xr2 + i + 3 * PARTS, pol);
            B3 = ldg_pin(xr3 + i + 3 * PARTS, pol);
        }
        const int i1 = i + PARTS;
#pragma unroll
        for (int e = 0; e < NEXP; e++) {
            ulonglong2 wv = wp[e * (DIM / 4) + i1];
            acc[e][0] = ffma2(y0.x, wv.x, ffma2(y0.y, wv.y, acc[e][0]));
            acc[e][1] = ffma2(y1.x, wv.x, ffma2(y1.y, wv.y, acc[e][1]));
            acc[e][2] = ffma2(y2.x, wv.x, ffma2(y2.y, wv.y, acc[e][2]));
            acc[e][3] = ffma2(y3.x, wv.x, ffma2(y3.y, wv.y, acc[e][3]));
        }
        i += 2 * PARTS;
    }

    // Reduce the 8 part-partials (consecutive lanes) via butterfly shuffles.
#pragma unroll
    for (int e = 0; e < NEXP; e++) {
#pragma unroll
        for (int t = 0; t < TOKS; t++) {
            unsigned long long v = acc[e][t];
            v = fadd2(v, __shfl_xor_sync(0xffffffffu, v, 1));
            v = fadd2(v, __shfl_xor_sync(0xffffffffu, v, 2));
            v = fadd2(v, __shfl_xor_sync(0xffffffffu, v, 4));
            acc[e][t] = v;
        }
    }

    if (part != 0) return;

    // Epilogue: one lane per group -> softmax + top-2 for its 4 tokens.
    float4 gv[2], iv[2];
    float* gvf = reinterpret_cast<float*>(gv);
    float* ivf = reinterpret_cast<float*>(iv);

#pragma unroll
    for (int t = 0; t < TOKS; t++) {
        float logits[NEXP];
        float m = -1e30f;
#pragma unroll
        for (int e = 0; e < NEXP; e++) {
            float lo = __uint_as_float((unsigned)(acc[e][t] & 0xffffffffull));
            float hi = __uint_as_float((unsigned)(acc[e][t] >> 32));
            logits[e] = lo + hi + sb[e];
            m = fmaxf(m, logits[e]);
        }
        float g[NEXP], s = 0.f;
#pragma unroll
        for (int e = 0; e < NEXP; e++) { g[e] = __expf(logits[e] - m); s += g[e]; }
        float inv = 1.0f / s;
#pragma unroll
        for (int e = 0; e < NEXP; e++) g[e] *= inv;

        // Top-2, strict '>' keeps lowest index on ties (matches jax.lax.top_k).
        int i1 = 0; float g1 = g[0];
#pragma unroll
        for (int e = 1; e < NEXP; e++) if (g[e] > g1) { g1 = g[e]; i1 = e; }
        int i2 = -1; float g2 = -1e30f;
#pragma unroll
        for (int e = 0; e < NEXP; e++) if (e != i1 && g[e] > g2) { g2 = g[e]; i2 = e; }

        gvf[2 * t + 0] = g1;
        gvf[2 * t + 1] = g2;
        ivf[2 * t + 0] = (float)i1;
        ivf[2 * t + 1] = (float)i2;
    }

    // Output: [0,2N) top-2 gates, [2N,4N) indices as fp32 (exact integers).
    float* og = out + (size_t)t0 * 2;                       // 32B aligned (t0 % 4 == 0)
    float* oi = out + (size_t)2 * n_tokens + (size_t)t0 * 2;
    if (t0 + TOKS <= n_tokens) {
        reinterpret_cast<float4*>(og)[0] = gv[0];
        reinterpret_cast<float4*>(og)[1] = gv[1];
        reinterpret_cast<float4*>(oi)[0] = iv[0];
        reinterpret_cast<float4*>(oi)[1] = iv[1];
    } else {
        for (int t = 0; t < TOKS && t0 + t < n_tokens; t++) {
            og[2 * t + 0] = gvf[2 * t + 0];
            og[2 * t + 1] = gvf[2 * t + 1];
            oi[2 * t + 0] = ivf[2 * t + 0];
            oi[2 * t + 1] = ivf[2 * t + 1];
        }
    }
}

extern "C" void kernel_launch(void* const* d_in, const int* in_sizes, int n_in,
                              void* d_out, int out_size) {
    const float* x = (const float*)d_in[0];
    const float* W = (const float*)d_in[1];
    const float* b = (const float*)d_in[2];
    float* out = (float*)d_out;

    int n_tokens = in_sizes[0] / DIM;                  // 128*197 = 25216
    int groups   = (n_tokens + TOKS - 1) / TOKS;       // 6304
    int threads  = groups * PARTS;                     // 50432
    int blocks   = (threads + TPB - 1) / TPB;          // 788

    Router_54932631716286_kernel<<<blocks, TPB>>>(x, W, b, out, n_tokens);
}